// round 2
// baseline (speedup 1.0000x reference)
#include <cuda_runtime.h>

// Problem constants (fixed by the reference: B=16, S=2048, D=768, fp32)
#define B_DIM 16
#define S_DIM 2048
#define D_DIM 768
#define V4    (D_DIM / 4)   // 192 float4 per row

// Segment-mean via per-CTA binary search on sorted per-row seg ids.
// One CTA per (word slot w, batch b). Thread 0 finds the run [start, start+cnt)
// with seg[b,p] == w and broadcasts via shared memory; all 192 threads then
// stream the run rows (each thread owns one float4 column).
__global__ __launch_bounds__(V4) void seg_mean_kernel(
    const float* __restrict__ x,    // [B, S, D]
    const int*   __restrict__ seg,  // [B, S] sorted non-decreasing per row
    float*       __restrict__ out)  // [B, S, D]
{
    const int w = blockIdx.x;   // output word slot
    const int b = blockIdx.y;
    const int t = threadIdx.x;  // float4 lane 0..191

    __shared__ int s_start, s_cnt;

    if (t == 0) {
        const int* __restrict__ srow = seg + b * S_DIM;
        // lower_bound: first idx with srow[idx] >= w
        int lo = 0, hi = S_DIM;
        while (lo < hi) {
            int m = (lo + hi) >> 1;
            if (__ldg(srow + m) < w) lo = m + 1; else hi = m;
        }
        const int start = lo;
        // upper_bound: first idx with srow[idx] > w
        hi = S_DIM;
        while (lo < hi) {
            int m = (lo + hi) >> 1;
            if (__ldg(srow + m) <= w) lo = m + 1; else hi = m;
        }
        s_start = start;
        s_cnt   = lo - start;
    }
    __syncthreads();

    const int start = s_start;
    const int cnt   = s_cnt;

    float4* o = reinterpret_cast<float4*>(
                    out + ((size_t)b * S_DIM + w) * D_DIM) + t;

    if (cnt == 0) {
        *o = make_float4(0.f, 0.f, 0.f, 0.f);
        return;
    }

    const float4* p = reinterpret_cast<const float4*>(
                          x + ((size_t)b * S_DIM + start) * D_DIM) + t;

    float4 acc = *p;
    if (cnt > 1) {
        // dual accumulators to expose a little more MLP on longer runs
        const float4* q = p + V4;            // next row, same column
        float4 acc2 = make_float4(0.f, 0.f, 0.f, 0.f);
        int i = 1;
        for (; i + 1 < cnt; i += 2) {
            const float4 v1 = q[0];
            const float4 v2 = q[V4];
            q += 2 * V4;
            acc.x  += v1.x; acc.y  += v1.y; acc.z  += v1.z; acc.w  += v1.w;
            acc2.x += v2.x; acc2.y += v2.y; acc2.z += v2.z; acc2.w += v2.w;
        }
        if (i < cnt) {
            const float4 v1 = q[0];
            acc.x += v1.x; acc.y += v1.y; acc.z += v1.z; acc.w += v1.w;
        }
        acc.x += acc2.x; acc.y += acc2.y; acc.z += acc2.z; acc.w += acc2.w;
    }

    const float inv = 1.0f / (float)cnt;
    acc.x *= inv; acc.y *= inv; acc.z *= inv; acc.w *= inv;
    *o = acc;
}

extern "C" void kernel_launch(void* const* d_in, const int* in_sizes, int n_in,
                              void* d_out, int out_size)
{
    const float* x   = (const float*)d_in[0];  // robert_embed [16,2048,768] f32
    const int*   seg = (const int*)  d_in[1];  // seg_ids      [16,2048]     i32
    float*       out = (float*)d_out;          // [16,2048,768] f32

    dim3 grid(S_DIM, B_DIM);
    seg_mean_kernel<<<grid, V4>>>(x, seg, out);
}

// round 3
// speedup vs baseline: 1.9495x; 1.9495x over previous
#include <cuda_runtime.h>

// Problem constants (fixed by the reference: B=16, S=2048, D=768, fp32)
#define B_DIM 16
#define S_DIM 2048
#define D_DIM 768
#define V4    (D_DIM / 4)   // 192 float4 per row
#define NSLOT (B_DIM * S_DIM)

// Scratch: run table per (b, w) output slot.
//   g_start[slot] = first input position of the run, or -1 if slot is empty
//   g_end[slot]   = one past the last input position (valid only if start>=0)
__device__ int g_start[NSLOT];
__device__ int g_end[NSLOT];

// Phase 1: embarrassingly parallel run detection on the sorted seg rows.
// Each thread owns one input position p. Every output slot is written by
// exactly one thread (run-start threads also fill the empty slots in the gap
// below their id), so no init pass and no atomics are needed.
__global__ __launch_bounds__(256) void mark_runs_kernel(
    const int* __restrict__ seg)   // [B, S] sorted non-decreasing per row
{
    const int idx = blockIdx.x * blockDim.x + threadIdx.x;
    if (idx >= NSLOT) return;
    const int b = idx >> 11;          // / S_DIM
    const int p = idx & (S_DIM - 1);  // % S_DIM

    const int* __restrict__ srow = seg + b * S_DIM;
    const int s    = __ldg(srow + p);
    const int prev = (p == 0)         ? -1    : __ldg(srow + p - 1);
    const int next = (p == S_DIM - 1) ? S_DIM : __ldg(srow + p + 1);  // sentinel > any id

    int* __restrict__ bstart = g_start + b * S_DIM;
    int* __restrict__ bend   = g_end   + b * S_DIM;

    if (s != prev) {
        bstart[s] = p;                       // run start
        for (int w = prev + 1; w < s; w++)   // empty slots below this run
            bstart[w] = -1;
    }
    if (s != next) {
        bend[s] = p + 1;                     // run end (exclusive)
        if (p == S_DIM - 1)                  // empty slots above the last run
            for (int w = s + 1; w < S_DIM; w++)
                bstart[w] = -1;
    }
}

// Phase 2: one CTA per (w, b) output row. Broadcast-load the run bounds
// (2 independent loads), then stream the run with coalesced float4 accesses.
__global__ __launch_bounds__(V4) void seg_mean_kernel(
    const float* __restrict__ x,    // [B, S, D]
    float*       __restrict__ out)  // [B, S, D]
{
    const int w = blockIdx.x;
    const int b = blockIdx.y;
    const int t = threadIdx.x;      // float4 lane 0..191

    const int slot  = b * S_DIM + w;
    const int start = __ldg(g_start + slot);
    const int end   = __ldg(g_end   + slot);   // garbage if start<0; never used

    float4* o = reinterpret_cast<float4*>(
                    out + ((size_t)b * S_DIM + w) * D_DIM) + t;

    if (start < 0) {
        *o = make_float4(0.f, 0.f, 0.f, 0.f);
        return;
    }
    const int cnt = end - start;

    const float4* p = reinterpret_cast<const float4*>(
                          x + ((size_t)b * S_DIM + start) * D_DIM) + t;

    float4 acc = *p;
    if (cnt > 1) {
        const float4* q = p + V4;
        float4 acc2 = make_float4(0.f, 0.f, 0.f, 0.f);
        int i = 1;
        for (; i + 1 < cnt; i += 2) {
            const float4 v1 = q[0];
            const float4 v2 = q[V4];
            q += 2 * V4;
            acc.x  += v1.x; acc.y  += v1.y; acc.z  += v1.z; acc.w  += v1.w;
            acc2.x += v2.x; acc2.y += v2.y; acc2.z += v2.z; acc2.w += v2.w;
        }
        if (i < cnt) {
            const float4 v1 = q[0];
            acc.x += v1.x; acc.y += v1.y; acc.z += v1.z; acc.w += v1.w;
        }
        acc.x += acc2.x; acc.y += acc2.y; acc.z += acc2.z; acc.w += acc2.w;
    }

    const float inv = 1.0f / (float)cnt;
    acc.x *= inv; acc.y *= inv; acc.z *= inv; acc.w *= inv;
    *o = acc;
}

extern "C" void kernel_launch(void* const* d_in, const int* in_sizes, int n_in,
                              void* d_out, int out_size)
{
    const float* x   = (const float*)d_in[0];  // robert_embed [16,2048,768] f32
    const int*   seg = (const int*)  d_in[1];  // seg_ids      [16,2048]     i32
    float*       out = (float*)d_out;          // [16,2048,768] f32

    mark_runs_kernel<<<(NSLOT + 255) / 256, 256>>>(seg);

    dim3 grid(S_DIM, B_DIM);
    seg_mean_kernel<<<grid, V4>>>(x, out);
}

// round 5
// speedup vs baseline: 2.7419x; 1.4065x over previous
#include <cuda_runtime.h>

// Problem constants (fixed by the reference: B=16, S=2048, D=768, fp32)
#define B_DIM 16
#define S_DIM 2048
#define D_DIM 768
#define NSLOT (B_DIM * S_DIM)
#define WPC   8                 // warps per CTA in phase 2
#define CPL   6                 // float4 columns per lane (768 / 32 / 4)

// Run table per (b, w) output slot: .x = run start (-1 if slot empty),
// .y = run end (exclusive). Packed so phase 2 needs ONE 8-byte load.
__device__ int2 g_run[NSLOT];

// Phase 1: parallel run detection on the sorted seg rows. Each thread owns
// one input position p. The run-START thread scans forward to find the run
// end (runs average ~1.6 long, L1-resident) and writes the packed entry;
// it also fills the empty slots in the id-gap below its run. The thread at
// the final position fills trailing empty slots. Every slot written exactly
// once; no atomics, no init pass.
__global__ __launch_bounds__(256) void mark_runs_kernel(
    const int* __restrict__ seg)   // [B, S] sorted non-decreasing per row
{
    const int idx = blockIdx.x * blockDim.x + threadIdx.x;
    if (idx >= NSLOT) return;
    const int b = idx >> 11;          // / S_DIM
    const int p = idx & (S_DIM - 1);  // % S_DIM

    const int* __restrict__ srow = seg + b * S_DIM;
    const int s    = __ldg(srow + p);
    const int prev = (p == 0) ? -1 : __ldg(srow + p - 1);

    int2* __restrict__ brun = g_run + b * S_DIM;

    if (s != prev) {
        int e = p + 1;
        while (e < S_DIM && __ldg(srow + e) == s) e++;
        brun[s] = make_int2(p, e);
        for (int w = prev + 1; w < s; w++)   // empty slots below this run
            brun[w] = make_int2(-1, 0);
    }
    if (p == S_DIM - 1) {                    // empty slots above the last run
        for (int w = s + 1; w < S_DIM; w++)
            brun[w] = make_int2(-1, 0);
    }
}

// Phase 2: one WARP per output slot. All lanes broadcast-load the packed run
// bounds, then each lane streams its 6 float4 columns over the run rows with
// 6 independent loads in flight. Streaming cache hints: touch-once data.
__global__ __launch_bounds__(32 * WPC) void seg_mean_kernel(
    const float* __restrict__ x,    // [B, S, D]
    float*       __restrict__ out)  // [B, S, D]
{
    const int warp = threadIdx.x >> 5;
    const int lane = threadIdx.x & 31;
    const int slot = blockIdx.x * WPC + warp;   // slot = b*S + w

    const int2 run = __ldg(g_run + slot);       // broadcast, one LDG.64

    float4* __restrict__ o =
        reinterpret_cast<float4*>(out + (size_t)slot * D_DIM) + lane;

    if (run.x < 0) {
        const float4 z = make_float4(0.f, 0.f, 0.f, 0.f);
        #pragma unroll
        for (int c = 0; c < CPL; c++) __stcs(o + c * 32, z);
        return;
    }
    const int cnt = run.y - run.x;
    const int b   = slot >> 11;

    const float4* __restrict__ p = reinterpret_cast<const float4*>(
        x + ((size_t)(b * S_DIM + run.x)) * D_DIM) + lane;

    float4 acc[CPL];
    #pragma unroll
    for (int c = 0; c < CPL; c++) acc[c] = __ldcs(p + c * 32);

    for (int i = 1; i < cnt; i++) {
        p += D_DIM / 4;                          // next row
        float4 v[CPL];
        #pragma unroll
        for (int c = 0; c < CPL; c++) v[c] = __ldcs(p + c * 32);
        #pragma unroll
        for (int c = 0; c < CPL; c++) {
            acc[c].x += v[c].x; acc[c].y += v[c].y;
            acc[c].z += v[c].z; acc[c].w += v[c].w;
        }
    }

    const float inv = 1.0f / (float)cnt;
    #pragma unroll
    for (int c = 0; c < CPL; c++) {
        acc[c].x *= inv; acc[c].y *= inv; acc[c].z *= inv; acc[c].w *= inv;
        __stcs(o + c * 32, acc[c]);
    }
}

extern "C" void kernel_launch(void* const* d_in, const int* in_sizes, int n_in,
                              void* d_out, int out_size)
{
    const float* x   = (const float*)d_in[0];  // robert_embed [16,2048,768] f32
    const int*   seg = (const int*)  d_in[1];  // seg_ids      [16,2048]     i32
    float*       out = (float*)d_out;          // [16,2048,768] f32

    mark_runs_kernel<<<(NSLOT + 255) / 256, 256>>>(seg);
    seg_mean_kernel<<<NSLOT / WPC, 32 * WPC>>>(x, out);
}

// round 6
// speedup vs baseline: 2.9110x; 1.0616x over previous
#include <cuda_runtime.h>

// Problem constants (fixed by the reference: B=16, S=2048, D=768, fp32)
#define B_DIM 16
#define S_DIM 2048
#define D_DIM 768
#define NSLOT (B_DIM * S_DIM)
#define GSIZE 64                // threads per output slot (2 warps)
#define GPC   4                 // groups per 256-thread CTA
#define CPL   3                 // float4 columns per thread (192 / 64)

// Run table per (b, w) output slot: .x = run start (-1 if slot empty),
// .y = run end (exclusive). Packed so phase 2 needs ONE 8-byte load.
// Written with default caching so it is L2-resident when phase 2 reads it.
__device__ int2 g_run[NSLOT];

// Phase 1: parallel run detection on the sorted seg rows. Each thread owns
// one input position p. The run-START thread scans forward to find the run
// end (runs average ~1.6, L1-resident) and writes the packed entry; it also
// fills the empty slots in the id-gap below its run. The thread at the final
// position fills trailing empty slots. Every slot written exactly once; no
// atomics, no init pass.
__global__ __launch_bounds__(256) void mark_runs_kernel(
    const int* __restrict__ seg)   // [B, S] sorted non-decreasing per row
{
    const int idx = blockIdx.x * blockDim.x + threadIdx.x;
    if (idx >= NSLOT) return;
    const int b = idx >> 11;          // / S_DIM
    const int p = idx & (S_DIM - 1);  // % S_DIM

    const int* __restrict__ srow = seg + b * S_DIM;
    const int s    = __ldg(srow + p);
    const int prev = (p == 0) ? -1 : __ldg(srow + p - 1);

    int2* __restrict__ brun = g_run + b * S_DIM;

    if (s != prev) {
        int e = p + 1;
        while (e < S_DIM && __ldg(srow + e) == s) e++;
        brun[s] = make_int2(p, e);
        for (int w = prev + 1; w < s; w++)   // empty slots below this run
            brun[w] = make_int2(-1, 0);
    }
    if (p == S_DIM - 1) {                    // empty slots above the last run
        for (int w = s + 1; w < S_DIM; w++)
            brun[w] = make_int2(-1, 0);
    }
}

// Phase 2: one 64-thread GROUP (2 warps) per output slot; each thread owns
// 3 float4 columns. Lower register pressure than warp-per-slot -> ~48 warps/SM
// occupancy -> more SM-level loads in flight. Streaming hints on x/out
// (touch-once, 201 MB > L2); run table reads hit L2 from phase 1.
__global__ __launch_bounds__(GSIZE * GPC) void seg_mean_kernel(
    const float* __restrict__ x,    // [B, S, D]
    float*       __restrict__ out)  // [B, S, D]
{
    const int g    = threadIdx.x >> 6;          // group in CTA, 0..3
    const int h    = threadIdx.x & (GSIZE - 1); // lane in group, 0..63
    const int slot = blockIdx.x * GPC + g;      // slot = b*S + w

    const int2 run = __ldg(g_run + slot);       // broadcast LDG.64, L2 hit

    float4* __restrict__ o =
        reinterpret_cast<float4*>(out + (size_t)slot * D_DIM) + h;

    if (run.x < 0) {
        const float4 z = make_float4(0.f, 0.f, 0.f, 0.f);
        #pragma unroll
        for (int c = 0; c < CPL; c++) __stcs(o + c * GSIZE, z);
        return;
    }
    const int cnt = run.y - run.x;
    const int b   = slot >> 11;

    const float4* __restrict__ p = reinterpret_cast<const float4*>(
        x + ((size_t)(b * S_DIM + run.x)) * D_DIM) + h;

    float4 acc[CPL];
    #pragma unroll
    for (int c = 0; c < CPL; c++) acc[c] = __ldcs(p + c * GSIZE);

    for (int i = 1; i < cnt; i++) {
        p += D_DIM / 4;                          // next row
        float4 v[CPL];
        #pragma unroll
        for (int c = 0; c < CPL; c++) v[c] = __ldcs(p + c * GSIZE);
        #pragma unroll
        for (int c = 0; c < CPL; c++) {
            acc[c].x += v[c].x; acc[c].y += v[c].y;
            acc[c].z += v[c].z; acc[c].w += v[c].w;
        }
    }

    const float inv = 1.0f / (float)cnt;
    #pragma unroll
    for (int c = 0; c < CPL; c++) {
        acc[c].x *= inv; acc[c].y *= inv; acc[c].z *= inv; acc[c].w *= inv;
        __stcs(o + c * GSIZE, acc[c]);
    }
}

extern "C" void kernel_launch(void* const* d_in, const int* in_sizes, int n_in,
                              void* d_out, int out_size)
{
    const float* x   = (const float*)d_in[0];  // robert_embed [16,2048,768] f32
    const int*   seg = (const int*)  d_in[1];  // seg_ids      [16,2048]     i32
    float*       out = (float*)d_out;          // [16,2048,768] f32

    mark_runs_kernel<<<(NSLOT + 255) / 256, 256>>>(seg);
    seg_mean_kernel<<<NSLOT / GPC, GSIZE * GPC>>>(x, out);
}

// round 7
// speedup vs baseline: 3.0576x; 1.0504x over previous
#include <cuda_runtime.h>
#include <limits.h>

// Problem constants (fixed by the reference: B=16, S=2048, D=768, fp32)
#define B_DIM 16
#define S_DIM 2048
#define D_DIM 768
#define NSLOT (B_DIM * S_DIM)
#define GSIZE 64                // threads per group (2 warps)
#define GPC   4                 // groups per 256-thread CTA
#define CPL   3                 // float4 columns per thread (192 / 64)

// Single fused kernel. One 64-thread group per INPUT position p.
//   - warp-parallel run detection: lane loads seg[p-1+lane]; shfl gives
//     prev/s, ballot gives the run end. One L1-resident load round, no
//     binary search, no scratch table, no second kernel.
//   - if s == prev: p is not a run start -> group exits (its row is read
//     by the run-start group). ~37% of groups exit after one load.
//   - run-start group streams rows [p, end) (coalesced float4, streaming
//     hints), writes mean to out[b, s], and zero-fills the empty output
//     slots in (prev, s). Group at p = S-1 also fills trailing empties.
// Every output slot is written exactly once; input read exactly once.
__global__ __launch_bounds__(GSIZE * GPC) void seg_mean_fused_kernel(
    const float* __restrict__ x,    // [B, S, D]
    const int*   __restrict__ seg,  // [B, S] sorted non-decreasing per row
    float*       __restrict__ out)  // [B, S, D]
{
    const int g    = threadIdx.x >> 6;          // group in CTA, 0..3
    const int h    = threadIdx.x & (GSIZE - 1); // lane in group, 0..63
    const int lane = h & 31;                    // lane in warp
    const int gidx = blockIdx.x * GPC + g;      // global group = b*S + p
    const int b    = gidx >> 11;
    const int p    = gidx & (S_DIM - 1);

    const int base = b * S_DIM;
    const int* __restrict__ srow = seg + base;

    // One parallel load covers positions p-1 .. p+30.
    const int idx = p - 1 + lane;
    int v;
    if (idx < 0)            v = -1;        // below-range sentinel (start of row)
    else if (idx >= S_DIM)  v = INT_MAX;   // above-range sentinel (forces mismatch)
    else                    v = __ldg(srow + idx);

    const int prev = __shfl_sync(0xffffffffu, v, 0);  // seg[p-1] (or -1)
    const int s    = __shfl_sync(0xffffffffu, v, 1);  // seg[p]

    const bool is_start = (s != prev);
    const bool is_last  = (p == S_DIM - 1);

    // Trailing empty slots handled by the last-position group regardless of
    // whether it is a run start.
    if (is_last) {
        const float4 z = make_float4(0.f, 0.f, 0.f, 0.f);
        for (int w = s + 1; w < S_DIM; w++) {
            float4* o = reinterpret_cast<float4*>(
                            out + (size_t)(base + w) * D_DIM) + h;
            #pragma unroll
            for (int c = 0; c < CPL; c++) __stcs(o + c * GSIZE, z);
        }
    }

    if (!is_start) return;

    // Zero-fill empty slots in the id-gap below this run.
    if (prev + 1 < s) {
        const float4 z = make_float4(0.f, 0.f, 0.f, 0.f);
        for (int w = prev + 1; w < s; w++) {
            float4* o = reinterpret_cast<float4*>(
                            out + (size_t)(base + w) * D_DIM) + h;
            #pragma unroll
            for (int c = 0; c < CPL; c++) __stcs(o + c * GSIZE, z);
        }
    }

    // Run end from ballot: first lane >= 2 whose id differs from s.
    const unsigned mism = __ballot_sync(0xffffffffu, v != s) & 0xFFFFFFFCu;
    int end;
    if (mism) {
        end = p - 1 + (__ffs(mism) - 1);          // position of first mismatch
    } else {
        end = p + 31;                              // p..p+30 all == s; scan on
        while (end < S_DIM && __ldg(srow + end) == s) end++;
    }
    const int cnt = end - p;

    // Stream rows [p, end): each thread owns 3 float4 columns.
    const float4* __restrict__ q = reinterpret_cast<const float4*>(
        x + (size_t)(base + p) * D_DIM) + h;

    float4 acc[CPL];
    #pragma unroll
    for (int c = 0; c < CPL; c++) acc[c] = __ldcs(q + c * GSIZE);

    for (int i = 1; i < cnt; i++) {
        q += D_DIM / 4;
        float4 t[CPL];
        #pragma unroll
        for (int c = 0; c < CPL; c++) t[c] = __ldcs(q + c * GSIZE);
        #pragma unroll
        for (int c = 0; c < CPL; c++) {
            acc[c].x += t[c].x; acc[c].y += t[c].y;
            acc[c].z += t[c].z; acc[c].w += t[c].w;
        }
    }

    const float inv = 1.0f / (float)cnt;
    float4* __restrict__ o = reinterpret_cast<float4*>(
                                 out + (size_t)(base + s) * D_DIM) + h;
    #pragma unroll
    for (int c = 0; c < CPL; c++) {
        acc[c].x *= inv; acc[c].y *= inv; acc[c].z *= inv; acc[c].w *= inv;
        __stcs(o + c * GSIZE, acc[c]);
    }
}

extern "C" void kernel_launch(void* const* d_in, const int* in_sizes, int n_in,
                              void* d_out, int out_size)
{
    const float* x   = (const float*)d_in[0];  // robert_embed [16,2048,768] f32
    const int*   seg = (const int*)  d_in[1];  // seg_ids      [16,2048]     i32
    float*       out = (float*)d_out;          // [16,2048,768] f32

    seg_mean_fused_kernel<<<NSLOT / GPC, GSIZE * GPC>>>(x, seg, out);
}